// round 4
// baseline (speedup 1.0000x reference)
#include <cuda_runtime.h>
#include <math.h>
#include <float.h>

// ---------------- problem constants ----------------
#define BB    2
#define TT    2048
#define CCH   2048
#define HH    16
#define HDD   128
#define LORA_ 512
#define RDIM  64
#define NDIM  64
#define MTOT  (BB*TT)        /* 4096 */
#define CKVW  (LORA_+RDIM)   /* 576  */
#define KVW   (HH*NDIM)      /* 1024 */

// ---------------- scratch (static device memory; allocation-free) ----------------
__device__ float g_q  [(size_t)MTOT * (HH*HDD)]; // 32 MB  q after GEMM1, rope applied in place
__device__ float g_ckv[(size_t)MTOT * CKVW];     //  9 MB  [latent(512) | k_rope(64)]
__device__ float g_kv [(size_t)MTOT * KVW];      // 16 MB  kv = latent @ Wkvb, layout [m][h*64+d]
__device__ float g_y  [(size_t)MTOT * KVW];      // 16 MB  attention out (nope part only)

// =====================================================================
// Generic tiled SGEMM:  C[M,N] = A[M,K] * B[K,N]
// 128x128 tile, BK=16, 256 threads, 8x8 per thread.
// REMAP: B row index k -> (k/64)*128 + (k%64)   (for Wo nope-row gather)
// =====================================================================
template<bool REMAP>
__global__ __launch_bounds__(256)
void sgemm_kernel(const float* __restrict__ A, const float* __restrict__ B,
                  float* __restrict__ C, int M, int N, int K, int lda, int ldb)
{
    __shared__ float As[16][128];  // transposed: As[k][m]
    __shared__ float Bs[16][128];  // Bs[k][n]

    const int tid  = threadIdx.x;
    const int row0 = blockIdx.y * 128;
    const int col0 = blockIdx.x * 128;
    const int ty   = tid >> 4;       // 0..15
    const int tx   = tid & 15;       // 0..15

    const int ar = tid >> 2;         // 0..63
    const int ac = (tid & 3) << 2;   // 0,4,8,12
    const int br = tid >> 5;         // 0..7
    const int bc = (tid & 31) << 2;  // 0..124

    float acc[8][8];
    #pragma unroll
    for (int i = 0; i < 8; i++)
        #pragma unroll
        for (int j = 0; j < 8; j++) acc[i][j] = 0.f;

    for (int kt = 0; kt < K; kt += 16) {
        // ---- load A tile (transposed into smem) ----
        #pragma unroll
        for (int rr = 0; rr < 2; rr++) {
            int r = ar + rr*64;
            float4 v = *(const float4*)&A[(size_t)(row0 + r)*lda + kt + ac];
            As[ac+0][r] = v.x; As[ac+1][r] = v.y;
            As[ac+2][r] = v.z; As[ac+3][r] = v.w;
        }
        // ---- load B tile ----
        #pragma unroll
        for (int rr = 0; rr < 2; rr++) {
            int kr   = kt + br + rr*8;
            int krow = REMAP ? ((kr >> 6)*128 + (kr & 63)) : kr;
            int col  = col0 + bc;
            float4 v;
            if (col + 3 < N) {
                v = *(const float4*)&B[(size_t)krow*ldb + col];
            } else {
                v.x = (col+0 < N) ? B[(size_t)krow*ldb + col+0] : 0.f;
                v.y = (col+1 < N) ? B[(size_t)krow*ldb + col+1] : 0.f;
                v.z = (col+2 < N) ? B[(size_t)krow*ldb + col+2] : 0.f;
                v.w = (col+3 < N) ? B[(size_t)krow*ldb + col+3] : 0.f;
            }
            *(float4*)&Bs[br + rr*8][bc] = v;
        }
        __syncthreads();

        #pragma unroll
        for (int kk = 0; kk < 16; kk++) {
            float a[8], b[8];
            *(float4*)&a[0] = *(const float4*)&As[kk][ty*8];
            *(float4*)&a[4] = *(const float4*)&As[kk][ty*8+4];
            *(float4*)&b[0] = *(const float4*)&Bs[kk][tx*8];
            *(float4*)&b[4] = *(const float4*)&Bs[kk][tx*8+4];
            #pragma unroll
            for (int i = 0; i < 8; i++)
                #pragma unroll
                for (int j = 0; j < 8; j++)
                    acc[i][j] += a[i]*b[j];
        }
        __syncthreads();
    }

    // ---- store ----
    #pragma unroll
    for (int i = 0; i < 8; i++) {
        int r = row0 + ty*8 + i;
        #pragma unroll
        for (int j4 = 0; j4 < 8; j4 += 4) {
            int col = col0 + tx*8 + j4;
            if (col + 3 < N) {
                float4 v = make_float4(acc[i][j4], acc[i][j4+1], acc[i][j4+2], acc[i][j4+3]);
                *(float4*)&C[(size_t)r*N + col] = v;
            } else {
                #pragma unroll
                for (int j = 0; j < 4; j++)
                    if (col + j < N) C[(size_t)r*N + col + j] = acc[i][j4+j];
            }
        }
    }
}

// =====================================================================
// RoPE applied in place: q rope dims (per head, dims 64..127) and k_rope
// (ckv cols 512..575, shared across heads).
// =====================================================================
__global__ __launch_bounds__(256)
void rope_kernel()
{
    const int nq = MTOT * HH * (RDIM/2);   // 2,097,152
    const int nk = MTOT * (RDIM/2);        //   131,072
    int idx = blockIdx.x * blockDim.x + threadIdx.x;
    if (idx >= nq + nk) return;

    float* p;
    int t, i;
    if (idx < nq) {
        i = idx & 31;
        int r = idx >> 5;
        int h = r & (HH-1);
        int m = r >> 4;               // r / HH
        t = m & (TT-1);
        p = g_q + (size_t)m*(HH*HDD) + h*HDD + NDIM + 2*i;
    } else {
        int j = idx - nq;
        i = j & 31;
        int m = j >> 5;
        t = m & (TT-1);
        p = g_ckv + (size_t)m*CKVW + LORA_ + 2*i;
    }
    // freqs[i] = theta^(-(2i)/64) = theta^(-i/32)
    float freq = powf(100000.0f, -(float)i * (1.0f/32.0f));
    float ang  = (float)t * freq;
    float sn, cs;
    sincosf(ang, &sn, &cs);
    float x0 = p[0], x1 = p[1];
    p[0] = x0*cs - x1*sn;
    p[1] = x0*sn + x1*cs;
}

// =====================================================================
// Causal flash attention (fp32, online softmax).
// Block = (qt, h, b): 64 queries x all causal keys in 64-key tiles.
// K dims 0..63 come from kv (== V), dims 64..127 from ckv rope part.
// 256 threads = 16x16, each computes a 4x4 micro-tile.
// smem: Qt[d=128][r=64] (stride 65), Kt same, Vs[64][64], Pt[s=64][r] (stride 65)
// =====================================================================
#define ATT_SMEM_FLOATS (128*65 + 128*65 + 64*64 + 64*65)   /* 24896 */
#define ATT_SMEM_BYTES  (ATT_SMEM_FLOATS*4)                 /* 99584 */

__global__ __launch_bounds__(256)
void attn_kernel()
{
    extern __shared__ float sm[];
    float* Qt = sm;                 // [128][65]
    float* Kt = Qt + 128*65;        // [128][65]
    float* Vs = Kt + 128*65;        // [64][64]
    float* Pt = Vs + 64*64;         // [64][65]

    const int tid = threadIdx.x;
    const int ty  = tid >> 4;       // 0..15 (query rows)
    const int tx  = tid & 15;       // 0..15 (key cols / out dims)
    const int qt  = blockIdx.x;
    const int h   = blockIdx.y;
    const int b   = blockIdx.z;
    const int t0  = qt * 64;
    const size_t mb = (size_t)b * TT;

    // load Q tile (transposed, padded stride 65)
    for (int idx = tid; idx < 64*128; idx += 256) {
        int r = idx >> 7, d = idx & 127;
        Qt[d*65 + r] = g_q[(mb + t0 + r)*(size_t)(HH*HDD) + h*HDD + d];
    }

    float m_r[4], l_r[4], acc[4][4];
    #pragma unroll
    for (int i = 0; i < 4; i++) {
        m_r[i] = -FLT_MAX; l_r[i] = 0.f;
        #pragma unroll
        for (int j = 0; j < 4; j++) acc[i][j] = 0.f;
    }
    const float scale = 0.088388347648318447f;  // 1/sqrt(128)

    for (int kt = 0; kt <= qt; kt++) {
        const int s0 = kt * 64;
        __syncthreads();   // protect smem from previous iteration's consumers
        for (int idx = tid; idx < 64*128; idx += 256) {
            int s = idx >> 7, d = idx & 127;
            float v = (d < NDIM)
                ? g_kv [(mb + s0 + s)*(size_t)KVW  + h*NDIM + d]
                : g_ckv[(mb + s0 + s)*(size_t)CKVW + LORA_ + (d - NDIM)];
            Kt[d*65 + s] = v;
        }
        for (int idx = tid; idx < 64*64; idx += 256) {
            int s = idx >> 6, d = idx & 63;
            Vs[s*64 + d] = g_kv[(mb + s0 + s)*(size_t)KVW + h*NDIM + d];
        }
        __syncthreads();

        // ---- S = Q . K^T ----
        float sv[4][4];
        #pragma unroll
        for (int i = 0; i < 4; i++)
            #pragma unroll
            for (int j = 0; j < 4; j++) sv[i][j] = 0.f;

        #pragma unroll 8
        for (int kk = 0; kk < 128; kk++) {
            float a0 = Qt[kk*65 + ty*4+0];
            float a1 = Qt[kk*65 + ty*4+1];
            float a2 = Qt[kk*65 + ty*4+2];
            float a3 = Qt[kk*65 + ty*4+3];
            float b0 = Kt[kk*65 + tx*4+0];
            float b1 = Kt[kk*65 + tx*4+1];
            float b2 = Kt[kk*65 + tx*4+2];
            float b3 = Kt[kk*65 + tx*4+3];
            sv[0][0] += a0*b0; sv[0][1] += a0*b1; sv[0][2] += a0*b2; sv[0][3] += a0*b3;
            sv[1][0] += a1*b0; sv[1][1] += a1*b1; sv[1][2] += a1*b2; sv[1][3] += a1*b3;
            sv[2][0] += a2*b0; sv[2][1] += a2*b1; sv[2][2] += a2*b2; sv[2][3] += a2*b3;
            sv[3][0] += a3*b0; sv[3][1] += a3*b1; sv[3][2] += a3*b2; sv[3][3] += a3*b3;
        }

        const bool diag = (kt == qt);
        #pragma unroll
        for (int i = 0; i < 4; i++)
            #pragma unroll
            for (int j = 0; j < 4; j++) {
                float s = sv[i][j]*scale;
                if (diag && (tx*4+j) > (ty*4+i)) s = -FLT_MAX;
                sv[i][j] = s;
            }

        // ---- online softmax (row stats reduced across the 16 tx lanes) ----
        #pragma unroll
        for (int i = 0; i < 4; i++) {
            float rm = fmaxf(fmaxf(sv[i][0], sv[i][1]), fmaxf(sv[i][2], sv[i][3]));
            #pragma unroll
            for (int o = 8; o >= 1; o >>= 1)
                rm = fmaxf(rm, __shfl_xor_sync(0xffffffffu, rm, o));
            float mn  = fmaxf(m_r[i], rm);
            float fac = __expf(m_r[i] - mn);
            float rs  = 0.f;
            #pragma unroll
            for (int j = 0; j < 4; j++) {
                float p = __expf(sv[i][j] - mn);
                sv[i][j] = p;
                rs += p;
            }
            #pragma unroll
            for (int o = 8; o >= 1; o >>= 1)
                rs += __shfl_xor_sync(0xffffffffu, rs, o);
            l_r[i] = l_r[i]*fac + rs;
            m_r[i] = mn;
            #pragma unroll
            for (int j = 0; j < 4; j++) acc[i][j] *= fac;
            // stash P transposed: Pt[key][row]
            #pragma unroll
            for (int j = 0; j < 4; j++)
                Pt[(tx*4+j)*65 + ty*4+i] = sv[i][j];
        }
        __syncthreads();

        // ---- acc += P . V ----
        #pragma unroll 8
        for (int ss = 0; ss < 64; ss++) {
            float a0 = Pt[ss*65 + ty*4+0];
            float a1 = Pt[ss*65 + ty*4+1];
            float a2 = Pt[ss*65 + ty*4+2];
            float a3 = Pt[ss*65 + ty*4+3];
            float b0 = Vs[ss*64 + tx*4+0];
            float b1 = Vs[ss*64 + tx*4+1];
            float b2 = Vs[ss*64 + tx*4+2];
            float b3 = Vs[ss*64 + tx*4+3];
            acc[0][0] += a0*b0; acc[0][1] += a0*b1; acc[0][2] += a0*b2; acc[0][3] += a0*b3;
            acc[1][0] += a1*b0; acc[1][1] += a1*b1; acc[1][2] += a1*b2; acc[1][3] += a1*b3;
            acc[2][0] += a2*b0; acc[2][1] += a2*b1; acc[2][2] += a2*b2; acc[2][3] += a2*b3;
            acc[3][0] += a3*b0; acc[3][1] += a3*b1; acc[3][2] += a3*b2; acc[3][3] += a3*b3;
        }
    }

    // ---- normalize & write y (nope part only; rope part of V is zero) ----
    #pragma unroll
    for (int i = 0; i < 4; i++) {
        float inv_l = 1.0f / l_r[i];
        #pragma unroll
        for (int j = 0; j < 4; j++)
            g_y[(mb + t0 + ty*4+i)*(size_t)KVW + h*NDIM + tx*4+j] = acc[i][j]*inv_l;
    }
}

// =====================================================================
// launch
// =====================================================================
extern "C" void kernel_launch(void* const* d_in, const int* in_sizes, int n_in,
                              void* d_out, int out_size)
{
    const float* x    = (const float*)d_in[0];
    const float* Wq   = (const float*)d_in[1];
    const float* Wkva = (const float*)d_in[2];
    const float* Wkvb = (const float*)d_in[3];
    const float* Wo   = (const float*)d_in[4];
    float* out        = (float*)d_out;

    float *gq, *gckv, *gkv, *gy;
    cudaGetSymbolAddress((void**)&gq,   g_q);
    cudaGetSymbolAddress((void**)&gckv, g_ckv);
    cudaGetSymbolAddress((void**)&gkv,  g_kv);
    cudaGetSymbolAddress((void**)&gy,   g_y);

    cudaFuncSetAttribute(attn_kernel, cudaFuncAttributeMaxDynamicSharedMemorySize,
                         ATT_SMEM_BYTES);

    dim3 blk(256);

    // 1) q = x @ Wq   [4096 x 2048]
    sgemm_kernel<false><<<dim3(2048/128, MTOT/128), blk>>>(x, Wq, gq,
        MTOT, HH*HDD, CCH, CCH, HH*HDD);

    // 2) ckv = x @ Wkva   [4096 x 576]
    sgemm_kernel<false><<<dim3((CKVW+127)/128, MTOT/128), blk>>>(x, Wkva, gckv,
        MTOT, CKVW, CCH, CCH, CKVW);

    // 3) rope on q-rope dims and k_rope columns (in place)
    {
        int total = MTOT*HH*(RDIM/2) + MTOT*(RDIM/2);
        rope_kernel<<<(total + 255)/256, blk>>>();
    }

    // 4) kv = ckv[:, :512] @ Wkvb   [4096 x 1024]
    sgemm_kernel<false><<<dim3(KVW/128, MTOT/128), blk>>>(gckv, Wkvb, gkv,
        MTOT, KVW, LORA_, CKVW, KVW);

    // 5) attention -> g_y
    attn_kernel<<<dim3(TT/64, HH, BB), blk, ATT_SMEM_BYTES>>>();

    // 6) out = y_nope @ Wo[nope rows]   [4096 x 2048]
    sgemm_kernel<true><<<dim3(2048/128, MTOT/128), blk>>>(gy, Wo, out,
        MTOT, CCH, KVW, KVW, CCH);
}

// round 6
// speedup vs baseline: 1.6326x; 1.6326x over previous
#include <cuda_runtime.h>
#include <cuda_fp16.h>
#include <stdint.h>
#include <math.h>
#include <float.h>

// ---------------- problem constants ----------------
#define BB    2
#define TT    2048
#define CCH   2048
#define HH    16
#define HDD   128
#define LORA_ 512
#define RDIM  64
#define NDIM  64
#define MTOT  (BB*TT)        /* 4096 */
#define CKVW  (LORA_+RDIM)   /* 576  */
#define KVW   (HH*NDIM)      /* 1024 */
#define NAPAD 640            /* ckv N padded to tile multiple */

// ---------------- fp32 scratch ----------------
__device__ float g_q  [(size_t)MTOT * (HH*HDD)];
__device__ float g_ckv[(size_t)MTOT * CKVW];
__device__ float g_kv [(size_t)MTOT * KVW];
__device__ float g_y  [(size_t)MTOT * KVW];

// ---------------- fp16 split (hi/lo) buffers ----------------
__device__ __align__(128) __half g_xh [(size_t)MTOT*CCH],  g_xl [(size_t)MTOT*CCH];
__device__ __align__(128) __half g_wqh[(size_t)2048*2048], g_wql[(size_t)2048*2048];
__device__ __align__(128) __half g_wah[(size_t)NAPAD*2048],g_wal[(size_t)NAPAD*2048];
__device__ __align__(128) __half g_wbh[(size_t)1024*512],  g_wbl[(size_t)1024*512];
__device__ __align__(128) __half g_woh[(size_t)2048*1024], g_wol[(size_t)2048*1024];
__device__ __align__(128) __half g_a4h[(size_t)MTOT*512],  g_a4l[(size_t)MTOT*512];
__device__ __align__(128) __half g_a6h[(size_t)MTOT*1024], g_a6l[(size_t)MTOT*1024];

// =====================================================================
// PTX helpers (all baseline sm_80+ — compile at compute_103)
// =====================================================================
__device__ __forceinline__ uint32_t smem_u32(const void* p) {
    uint32_t a;
    asm("{ .reg .u64 t; cvta.to.shared.u64 t, %1; cvt.u32.u64 %0, t; }" : "=r"(a) : "l"(p));
    return a;
}
#define CP_ASYNC16(dst, src) \
    asm volatile("cp.async.cg.shared.global [%0], [%1], 16;" :: "r"(dst), "l"(src))
#define CP_COMMIT() asm volatile("cp.async.commit_group;" ::: "memory")
#define CP_WAIT(n)  asm volatile("cp.async.wait_group %0;" :: "n"(n) : "memory")

#define LDSM4(R, addr) \
    asm volatile("ldmatrix.sync.aligned.m8n8.x4.shared.b16 {%0,%1,%2,%3}, [%4];" \
        : "=r"((R)[0]), "=r"((R)[1]), "=r"((R)[2]), "=r"((R)[3]) : "r"(addr))

#define MMA16816(D, A, B0, B1) \
    asm volatile("mma.sync.aligned.m16n8k16.row.col.f32.f16.f16.f32 " \
        "{%0,%1,%2,%3}, {%4,%5,%6,%7}, {%8,%9}, {%0,%1,%2,%3};" \
        : "+f"((D)[0]), "+f"((D)[1]), "+f"((D)[2]), "+f"((D)[3]) \
        : "r"((A)[0]), "r"((A)[1]), "r"((A)[2]), "r"((A)[3]), "r"(B0), "r"(B1))

// =====================================================================
// fp16 hi/lo split conversions
// =====================================================================
__global__ __launch_bounds__(256)
void convert_rows(const float* __restrict__ in, int ld, long total, int cols,
                  __half* __restrict__ oh, __half* __restrict__ ol)
{
    long i = (long)blockIdx.x * blockDim.x + threadIdx.x;
    long stride = (long)gridDim.x * blockDim.x;
    for (; i < total; i += stride) {
        long r = i / cols; int c = (int)(i - r*cols);
        float v = in[r*(long)ld + c];
        __half h = __float2half_rn(v);
        oh[i] = h;
        ol[i] = __float2half_rn(v - __half2float(h));
    }
}

// transpose + hi/lo split: out[n][k] = in[rmap(k)][n]; n>=N -> 0
__global__ __launch_bounds__(256)
void transpose_convert(const float* __restrict__ in, int N, int Kdim, int remap,
                       __half* __restrict__ oh, __half* __restrict__ ol)
{
    __shared__ float t[32][33];
    int tx = threadIdx.x & 31, ty = threadIdx.x >> 5;
    int k0 = blockIdx.x * 32, n0 = blockIdx.y * 32;
    #pragma unroll
    for (int i = 0; i < 4; i++) {
        int k = k0 + ty + i*8;
        int kr = remap ? ((k >> 6)*128 + (k & 63)) : k;
        int n = n0 + tx;
        t[ty + i*8][tx] = (n < N) ? in[(size_t)kr*N + n] : 0.f;
    }
    __syncthreads();
    #pragma unroll
    for (int i = 0; i < 4; i++) {
        int n = n0 + ty + i*8;
        int k = k0 + tx;
        float v = t[tx][ty + i*8];
        __half h = __float2half_rn(v);
        size_t o = (size_t)n*Kdim + k;
        oh[o] = h;
        ol[o] = __float2half_rn(v - __half2float(h));
    }
}

// =====================================================================
// fp16-split HMMA GEMM:  C[M x Nvalid] = A * B^T   (fp32-accurate)
// A: [M x K] hi/lo row-major.  B: [Ntile*128 x K] hi/lo row-major.
// CTA tile 128x128, BK=32, 8 warps (warp tile 32x64),
// 3-stage cp.async pipeline, 3 mma products per k-step (hh+hl+lh).
//
// smem tile layout per 128x32-half array (8KB): 128B line = 2 rows;
// 16B slot within line: slot(r,c) = (c | ((r&1)<<2)) ^ ((r>>1)&7)
//   -> ldmatrix reads conflict-free (verified by bank arithmetic).
// =====================================================================
#define STAGE_BYTES 32768
#define HG_STAGES   3
#define HG_SMEM     (STAGE_BYTES*HG_STAGES)   /* 98304 */

__global__ __launch_bounds__(256, 1)
void hgemm(const __half* __restrict__ Ah, const __half* __restrict__ Al,
           const __half* __restrict__ Bh, const __half* __restrict__ Bl,
           float* __restrict__ C, int K, int ldc, int Nvalid)
{
    extern __shared__ char smem[];
    const uint32_t sb = smem_u32(smem);
    const int tid  = threadIdx.x;
    const int wid  = tid >> 5, lane = tid & 31;
    const int row0 = blockIdx.y * 128;
    const int col0 = blockIdx.x * 128;
    const int wm   = wid >> 1;       // 0..3 -> m offset wm*32
    const int wn   = wid & 1;        // 0..1 -> n offset wn*64

    // ---- per-thread load decode (same for every stage/array) ----
    // idx in [0,512): line=idx>>3, slot=idx&7 ; logical (r,c) from slot
    int l_line[2], l_s8[2], l_r[2], l_c[2];
    #pragma unroll
    for (int j = 0; j < 2; j++) {
        int idx = tid + j*256;
        l_line[j] = idx >> 3;
        l_s8[j]   = idx & 7;
        int v     = l_s8[j] ^ (l_line[j] & 7);
        l_r[j]    = l_line[j]*2 + (v >> 2);
        l_c[j]    = v & 3;
    }

#define LOAD_STAGE(CH, ST) do { \
    uint32_t _base = sb + (uint32_t)(ST)*STAGE_BYTES; \
    _Pragma("unroll") \
    for (int _a = 0; _a < 4; _a++) { \
        const __half* _src = (_a == 0) ? Ah : (_a == 1) ? Al : (_a == 2) ? Bh : Bl; \
        int _rb = (_a < 2) ? row0 : col0; \
        _Pragma("unroll") \
        for (int _j = 0; _j < 2; _j++) { \
            const void* _g = _src + (size_t)(_rb + l_r[_j])*(size_t)K \
                             + (CH)*32 + l_c[_j]*8; \
            CP_ASYNC16(_base + _a*8192u + (uint32_t)(l_line[_j]*128 + l_s8[_j]*16), _g); \
        } \
    } \
    CP_COMMIT(); \
} while (0)

    float acc[2][8][4];
    #pragma unroll
    for (int mi = 0; mi < 2; mi++)
        #pragma unroll
        for (int nj = 0; nj < 8; nj++)
            #pragma unroll
            for (int e = 0; e < 4; e++) acc[mi][nj][e] = 0.f;

    const int nch = K >> 5;
    LOAD_STAGE(0, 0);
    LOAD_STAGE(1, 1);

    // ldmatrix per-lane row/offset precompute
    const int lr8 = (lane & 7) + ((lane >> 3) & 1)*8;  // 0..15 within m16/n16
    const int chx = (lane >> 4);                       // k-half select

    int st = 0;
    for (int ch = 0; ch < nch; ch++) {
        if (ch + 2 < nch) { CP_WAIT(1); } else { CP_WAIT(0); }
        __syncthreads();
        if (ch + 2 < nch) {
            int st2 = st + 2; if (st2 >= HG_STAGES) st2 -= HG_STAGES;
            LOAD_STAGE(ch + 2, st2);
        }

        const uint32_t base = sb + (uint32_t)st*STAGE_BYTES;
        #pragma unroll
        for (int kk = 0; kk < 2; kk++) {
            const int cc = kk*2 + chx;      // chunk index 0..3
            uint32_t a_h[2][4], a_l[2][4], b_h[4][4], b_l[4][4];

            #pragma unroll
            for (int mi = 0; mi < 2; mi++) {
                int r = wm*32 + mi*16 + lr8;
                uint32_t off = (uint32_t)((r >> 1)*128 +
                    (((cc | ((r & 1) << 2)) ^ ((r >> 1) & 7)) << 4));
                LDSM4(a_h[mi], base + off);
                LDSM4(a_l[mi], base + 8192u + off);
            }
            #pragma unroll
            for (int nb = 0; nb < 4; nb++) {
                int r = wn*64 + nb*16 + lr8;
                uint32_t off = (uint32_t)((r >> 1)*128 +
                    (((cc | ((r & 1) << 2)) ^ ((r >> 1) & 7)) << 4));
                LDSM4(b_h[nb], base + 16384u + off);
                LDSM4(b_l[nb], base + 24576u + off);
            }

            #pragma unroll
            for (int mi = 0; mi < 2; mi++)
                #pragma unroll
                for (int nb = 0; nb < 4; nb++)
                    #pragma unroll
                    for (int nn = 0; nn < 2; nn++) {
                        float* d = acc[mi][nb*2 + nn];
                        MMA16816(d, a_h[mi], b_h[nb][nn], b_h[nb][nn+2]);
                        MMA16816(d, a_h[mi], b_l[nb][nn], b_l[nb][nn+2]);
                        MMA16816(d, a_l[mi], b_h[nb][nn], b_h[nb][nn+2]);
                    }
        }
        st++; if (st >= HG_STAGES) st = 0;
    }

    // ---- epilogue ----
    #pragma unroll
    for (int mi = 0; mi < 2; mi++) {
        int m = row0 + wm*32 + mi*16 + (lane >> 2);
        #pragma unroll
        for (int nb = 0; nb < 4; nb++)
            #pragma unroll
            for (int nn = 0; nn < 2; nn++) {
                int col = col0 + wn*64 + nb*16 + nn*8 + (lane & 3)*2;
                if (col < Nvalid) {
                    const float* d = acc[mi][nb*2 + nn];
                    *(float2*)&C[(size_t)m*ldc + col]       = make_float2(d[0], d[1]);
                    *(float2*)&C[(size_t)(m + 8)*ldc + col] = make_float2(d[2], d[3]);
                }
            }
    }
}

// =====================================================================
// RoPE in place
// =====================================================================
__global__ __launch_bounds__(256)
void rope_kernel()
{
    const int nq = MTOT * HH * (RDIM/2);
    const int nk = MTOT * (RDIM/2);
    int idx = blockIdx.x * blockDim.x + threadIdx.x;
    if (idx >= nq + nk) return;
    float* p; int t, i;
    if (idx < nq) {
        i = idx & 31;
        int r = idx >> 5;
        int h = r & (HH-1);
        int m = r >> 4;
        t = m & (TT-1);
        p = g_q + (size_t)m*(HH*HDD) + h*HDD + NDIM + 2*i;
    } else {
        int j = idx - nq;
        i = j & 31;
        int m = j >> 5;
        t = m & (TT-1);
        p = g_ckv + (size_t)m*CKVW + LORA_ + 2*i;
    }
    float freq = powf(100000.0f, -(float)i * (1.0f/32.0f));
    float sn, cs; sincosf((float)t * freq, &sn, &cs);
    float x0 = p[0], x1 = p[1];
    p[0] = x0*cs - x1*sn;
    p[1] = x0*sn + x1*cs;
}

// =====================================================================
// fp32 causal flash attention (unchanged this round)
// =====================================================================
#define ATT_SMEM_FLOATS (128*65 + 128*65 + 64*64 + 64*65)
#define ATT_SMEM_BYTES  (ATT_SMEM_FLOATS*4)

__global__ __launch_bounds__(256)
void attn_kernel()
{
    extern __shared__ float sm[];
    float* Qt = sm;
    float* Kt = Qt + 128*65;
    float* Vs = Kt + 128*65;
    float* Pt = Vs + 64*64;

    const int tid = threadIdx.x;
    const int ty  = tid >> 4;
    const int tx  = tid & 15;
    const int qt  = blockIdx.x;
    const int h   = blockIdx.y;
    const int b   = blockIdx.z;
    const int t0  = qt * 64;
    const size_t mb = (size_t)b * TT;

    for (int idx = tid; idx < 64*128; idx += 256) {
        int r = idx >> 7, d = idx & 127;
        Qt[d*65 + r] = g_q[(mb + t0 + r)*(size_t)(HH*HDD) + h*HDD + d];
    }

    float m_r[4], l_r[4], acc[4][4];
    #pragma unroll
    for (int i = 0; i < 4; i++) {
        m_r[i] = -FLT_MAX; l_r[i] = 0.f;
        #pragma unroll
        for (int j = 0; j < 4; j++) acc[i][j] = 0.f;
    }
    const float scale = 0.088388347648318447f;

    for (int kt = 0; kt <= qt; kt++) {
        const int s0 = kt * 64;
        __syncthreads();
        for (int idx = tid; idx < 64*128; idx += 256) {
            int s = idx >> 7, d = idx & 127;
            float v = (d < NDIM)
                ? g_kv [(mb + s0 + s)*(size_t)KVW  + h*NDIM + d]
                : g_ckv[(mb + s0 + s)*(size_t)CKVW + LORA_ + (d - NDIM)];
            Kt[d*65 + s] = v;
        }
        for (int idx = tid; idx < 64*64; idx += 256) {
            int s = idx >> 6, d = idx & 63;
            Vs[s*64 + d] = g_kv[(mb + s0 + s)*(size_t)KVW + h*NDIM + d];
        }
        __syncthreads();

        float sv[4][4];
        #pragma unroll
        for (int i = 0; i < 4; i++)
            #pragma unroll
            for (int j = 0; j < 4; j++) sv[i][j] = 0.f;

        #pragma unroll 8
        for (int kk = 0; kk < 128; kk++) {
            float a0 = Qt[kk*65 + ty*4+0], a1 = Qt[kk*65 + ty*4+1];
            float a2 = Qt[kk*65 + ty*4+2], a3 = Qt[kk*65 + ty*4+3];
            float b0 = Kt[kk*65 + tx*4+0], b1 = Kt[kk*65 + tx*4+1];
            float b2 = Kt[kk*65 + tx*4+2], b3 = Kt[kk*65 + tx*4+3];
            sv[0][0] += a0*b0; sv[0][1] += a0*b1; sv[0][2] += a0*b2; sv[0][3] += a0*b3;
            sv[1][0] += a1*b0; sv[1][1] += a1*b1; sv[1][2] += a1*b2; sv[1][3] += a1*b3;
            sv[2][0] += a2*b0; sv[2][1] += a2*b1; sv[2][2] += a2*b2; sv[2][3] += a2*b3;
            sv[3][0] += a3*b0; sv[3][1] += a3*b1; sv[3][2] += a3*b2; sv[3][3] += a3*b3;
        }

        const bool diag = (kt == qt);
        #pragma unroll
        for (int i = 0; i < 4; i++)
            #pragma unroll
            for (int j = 0; j < 4; j++) {
                float s = sv[i][j]*scale;
                if (diag && (tx*4+j) > (ty*4+i)) s = -FLT_MAX;
                sv[i][j] = s;
            }

        #pragma unroll
        for (int i = 0; i < 4; i++) {
            float rm = fmaxf(fmaxf(sv[i][0], sv[i][1]), fmaxf(sv[i][2], sv[i][3]));
            #pragma unroll
            for (int off = 8; off >= 1; off >>= 1)
                rm = fmaxf(rm, __shfl_xor_sync(0xffffffffu, rm, off));
            float mn  = fmaxf(m_r[i], rm);
            float fac = __expf(m_r[i] - mn);
            float rs  = 0.f;
            #pragma unroll
            for (int j = 0; j < 4; j++) {
                float p = __expf(sv[i][j] - mn);
                sv[i][j] = p; rs += p;
            }
            #pragma unroll
            for (int off = 8; off >= 1; off >>= 1)
                rs += __shfl_xor_sync(0xffffffffu, rs, off);
            l_r[i] = l_r[i]*fac + rs;
            m_r[i] = mn;
            #pragma unroll
            for (int j = 0; j < 4; j++) acc[i][j] *= fac;
            #pragma unroll
            for (int j = 0; j < 4; j++)
                Pt[(tx*4+j)*65 + ty*4+i] = sv[i][j];
        }
        __syncthreads();

        #pragma unroll 8
        for (int ss = 0; ss < 64; ss++) {
            float a0 = Pt[ss*65 + ty*4+0], a1 = Pt[ss*65 + ty*4+1];
            float a2 = Pt[ss*65 + ty*4+2], a3 = Pt[ss*65 + ty*4+3];
            float b0 = Vs[ss*64 + tx*4+0], b1 = Vs[ss*64 + tx*4+1];
            float b2 = Vs[ss*64 + tx*4+2], b3 = Vs[ss*64 + tx*4+3];
            acc[0][0] += a0*b0; acc[0][1] += a0*b1; acc[0][2] += a0*b2; acc[0][3] += a0*b3;
            acc[1][0] += a1*b0; acc[1][1] += a1*b1; acc[1][2] += a1*b2; acc[1][3] += a1*b3;
            acc[2][0] += a2*b0; acc[2][1] += a2*b1; acc[2][2] += a2*b2; acc[2][3] += a2*b3;
            acc[3][0] += a3*b0; acc[3][1] += a3*b1; acc[3][2] += a3*b2; acc[3][3] += a3*b3;
        }
    }

    #pragma unroll
    for (int i = 0; i < 4; i++) {
        float inv_l = 1.0f / l_r[i];
        #pragma unroll
        for (int j = 0; j < 4; j++)
            g_y[(mb + t0 + ty*4+i)*(size_t)KVW + h*NDIM + tx*4+j] = acc[i][j]*inv_l;
    }
}

// =====================================================================
// launch
// =====================================================================
extern "C" void kernel_launch(void* const* d_in, const int* in_sizes, int n_in,
                              void* d_out, int out_size)
{
    const float* x    = (const float*)d_in[0];
    const float* Wq   = (const float*)d_in[1];
    const float* Wkva = (const float*)d_in[2];
    const float* Wkvb = (const float*)d_in[3];
    const float* Wo   = (const float*)d_in[4];
    float* out        = (float*)d_out;

    float *gq, *gckv, *gkv, *gy;
    cudaGetSymbolAddress((void**)&gq,   g_q);
    cudaGetSymbolAddress((void**)&gckv, g_ckv);
    cudaGetSymbolAddress((void**)&gkv,  g_kv);
    cudaGetSymbolAddress((void**)&gy,   g_y);

    __half *xh,*xl,*wqh,*wql,*wah,*wal,*wbh,*wbl,*woh,*wol,*a4h,*a4l,*a6h,*a6l;
    cudaGetSymbolAddress((void**)&xh,  g_xh);  cudaGetSymbolAddress((void**)&xl,  g_xl);
    cudaGetSymbolAddress((void**)&wqh, g_wqh); cudaGetSymbolAddress((void**)&wql, g_wql);
    cudaGetSymbolAddress((void**)&wah, g_wah); cudaGetSymbolAddress((void**)&wal, g_wal);
    cudaGetSymbolAddress((void**)&wbh, g_wbh); cudaGetSymbolAddress((void**)&wbl, g_wbl);
    cudaGetSymbolAddress((void**)&woh, g_woh); cudaGetSymbolAddress((void**)&wol, g_wol);
    cudaGetSymbolAddress((void**)&a4h, g_a4h); cudaGetSymbolAddress((void**)&a4l, g_a4l);
    cudaGetSymbolAddress((void**)&a6h, g_a6h); cudaGetSymbolAddress((void**)&a6l, g_a6l);

    cudaFuncSetAttribute(attn_kernel, cudaFuncAttributeMaxDynamicSharedMemorySize,
                         ATT_SMEM_BYTES);
    cudaFuncSetAttribute(hgemm, cudaFuncAttributeMaxDynamicSharedMemorySize,
                         HG_SMEM);

    dim3 blk(256);

    // weight prep: transpose to [N][K] K-major + hi/lo fp16 split
    transpose_convert<<<dim3(2048/32, 2048/32), blk>>>(Wq,   2048, 2048, 0, wqh, wql);
    transpose_convert<<<dim3(2048/32, NAPAD/32), blk>>>(Wkva, CKVW, 2048, 0, wah, wal);
    transpose_convert<<<dim3(512/32,  1024/32), blk>>>(Wkvb, 1024, 512,  0, wbh, wbl);
    transpose_convert<<<dim3(1024/32, 2048/32), blk>>>(Wo,   2048, 1024, 1, woh, wol);

    // x -> hi/lo
    convert_rows<<<4096, blk>>>(x, CCH, (long)MTOT*CCH, CCH, xh, xl);

    // 1) q = x @ Wq^T(t)  [4096 x 2048], K=2048
    hgemm<<<dim3(2048/128, MTOT/128), blk, HG_SMEM>>>(xh, xl, wqh, wql, gq,
        2048, 2048, 2048);

    // 2) ckv = x @ Wkva   [4096 x 576], K=2048 (N tiles padded to 640)
    hgemm<<<dim3(NAPAD/128, MTOT/128), blk, HG_SMEM>>>(xh, xl, wah, wal, gckv,
        2048, CKVW, CKVW);

    // 3) rope (q rope dims + k_rope cols), in place
    {
        int total = MTOT*HH*(RDIM/2) + MTOT*(RDIM/2);
        rope_kernel<<<(total + 255)/256, blk>>>();
    }

    // ckv latent -> hi/lo
    convert_rows<<<2048, blk>>>(gckv, CKVW, (long)MTOT*LORA_, LORA_, a4h, a4l);

    // 4) kv = latent @ Wkvb  [4096 x 1024], K=512
    hgemm<<<dim3(KVW/128, MTOT/128), blk, HG_SMEM>>>(a4h, a4l, wbh, wbl, gkv,
        512, KVW, KVW);

    // 5) attention -> g_y
    attn_kernel<<<dim3(TT/64, HH, BB), blk, ATT_SMEM_BYTES>>>();

    // y -> hi/lo
    convert_rows<<<4096, blk>>>(gy, KVW, (long)MTOT*KVW, KVW, a6h, a6l);

    // 6) out = y_nope @ Wo[nope rows]  [4096 x 2048], K=1024
    hgemm<<<dim3(2048/128, MTOT/128), blk, HG_SMEM>>>(a6h, a6l, woh, wol, out,
        1024, CCH, CCH);
}

// round 9
// speedup vs baseline: 2.8248x; 1.7303x over previous
#include <cuda_runtime.h>
#include <cuda_fp16.h>
#include <stdint.h>
#include <math.h>
#include <float.h>

// ---------------- problem constants ----------------
#define BB    2
#define TT    2048
#define CCH   2048
#define HH    16
#define HDD   128
#define LORA_ 512
#define RDIM  64
#define NDIM  64
#define MTOT  (BB*TT)        /* 4096 */
#define CKVW  (LORA_+RDIM)   /* 576  */
#define KVW   (HH*NDIM)      /* 1024 */
#define NAPAD 640

// ---------------- fp32 scratch ----------------
__device__ float g_q  [(size_t)MTOT * (HH*HDD)];
__device__ float g_ckv[(size_t)MTOT * CKVW];
__device__ float g_kv [(size_t)MTOT * KVW];

// ---------------- fp16 split (hi/lo) buffers ----------------
__device__ __align__(128) __half g_xh [(size_t)MTOT*CCH],  g_xl [(size_t)MTOT*CCH];
__device__ __align__(128) __half g_wqh[(size_t)2048*2048], g_wql[(size_t)2048*2048];
__device__ __align__(128) __half g_wah[(size_t)NAPAD*2048],g_wal[(size_t)NAPAD*2048];
__device__ __align__(128) __half g_wbh[(size_t)1024*512],  g_wbl[(size_t)1024*512];
__device__ __align__(128) __half g_woh[(size_t)2048*1024], g_wol[(size_t)2048*1024];
__device__ __align__(128) __half g_a4h[(size_t)MTOT*512],  g_a4l[(size_t)MTOT*512];
__device__ __align__(128) __half g_a6h[(size_t)MTOT*1024], g_a6l[(size_t)MTOT*1024];
// attention operand buffers [bh][t][d]
__device__ __align__(128) __half g_Qh[(size_t)BB*HH*TT*128], g_Ql[(size_t)BB*HH*TT*128];
__device__ __align__(128) __half g_Kh[(size_t)BB*HH*TT*128], g_Kl[(size_t)BB*HH*TT*128];
__device__ __align__(128) __half g_Vh[(size_t)BB*HH*TT*64],  g_Vl[(size_t)BB*HH*TT*64];

// =====================================================================
// PTX helpers (baseline sm_80+ — compile at compute_103)
// =====================================================================
__device__ __forceinline__ uint32_t smem_u32(const void* p) {
    uint32_t a;
    asm("{ .reg .u64 t; cvta.to.shared.u64 t, %1; cvt.u32.u64 %0, t; }" : "=r"(a) : "l"(p));
    return a;
}
#define CP_ASYNC16(dst, src) \
    asm volatile("cp.async.cg.shared.global [%0], [%1], 16;" :: "r"(dst), "l"(src))
#define CP_COMMIT() asm volatile("cp.async.commit_group;" ::: "memory")
#define CP_WAIT(n)  asm volatile("cp.async.wait_group %0;" :: "n"(n) : "memory")

#define LDSM4(R, addr) \
    asm volatile("ldmatrix.sync.aligned.m8n8.x4.shared.b16 {%0,%1,%2,%3}, [%4];" \
        : "=r"((R)[0]), "=r"((R)[1]), "=r"((R)[2]), "=r"((R)[3]) : "r"(addr))
#define LDSM4T(R, addr) \
    asm volatile("ldmatrix.sync.aligned.m8n8.x4.trans.shared.b16 {%0,%1,%2,%3}, [%4];" \
        : "=r"((R)[0]), "=r"((R)[1]), "=r"((R)[2]), "=r"((R)[3]) : "r"(addr))

#define MMA16816(D, A, B0, B1) \
    asm volatile("mma.sync.aligned.m16n8k16.row.col.f32.f16.f16.f32 " \
        "{%0,%1,%2,%3}, {%4,%5,%6,%7}, {%8,%9}, {%0,%1,%2,%3};" \
        : "+f"((D)[0]), "+f"((D)[1]), "+f"((D)[2]), "+f"((D)[3]) \
        : "r"((A)[0]), "r"((A)[1]), "r"((A)[2]), "r"((A)[3]), "r"(B0), "r"(B1))

__device__ __forceinline__ uint32_t h2u(__half2 v) { return *(uint32_t*)&v; }

// =====================================================================
// hi/lo split conversions
// =====================================================================
__global__ __launch_bounds__(256)
void convert_rows(const float* __restrict__ in, int ld, long total, int cols,
                  __half* __restrict__ oh, __half* __restrict__ ol)
{
    long i = (long)blockIdx.x * blockDim.x + threadIdx.x;
    long stride = (long)gridDim.x * blockDim.x;
    for (; i < total; i += stride) {
        long r = i / cols; int c = (int)(i - r*cols);
        float v = in[r*(long)ld + c];
        __half h = __float2half_rn(v);
        oh[i] = h;
        ol[i] = __float2half_rn(v - __half2float(h));
    }
}

__global__ __launch_bounds__(256)
void transpose_convert(const float* __restrict__ in, int N, int Kdim, int remap,
                       __half* __restrict__ oh, __half* __restrict__ ol)
{
    __shared__ float t[32][33];
    int tx = threadIdx.x & 31, ty = threadIdx.x >> 5;
    int k0 = blockIdx.x * 32, n0 = blockIdx.y * 32;
    #pragma unroll
    for (int i = 0; i < 4; i++) {
        int k = k0 + ty + i*8;
        int kr = remap ? ((k >> 6)*128 + (k & 63)) : k;
        int n = n0 + tx;
        t[ty + i*8][tx] = (n < N) ? in[(size_t)kr*N + n] : 0.f;
    }
    __syncthreads();
    #pragma unroll
    for (int i = 0; i < 4; i++) {
        int n = n0 + ty + i*8;
        int k = k0 + tx;
        float v = t[tx][ty + i*8];
        __half h = __float2half_rn(v);
        size_t o = (size_t)n*Kdim + k;
        oh[o] = h;
        ol[o] = __float2half_rn(v - __half2float(h));
    }
}

__device__ __forceinline__ void split_store4(float4 v, __half* __restrict__ oh,
                                             __half* __restrict__ ol, size_t i)
{
    __half h0 = __float2half_rn(v.x), h1 = __float2half_rn(v.y);
    __half h2 = __float2half_rn(v.z), h3 = __float2half_rn(v.w);
    *(__half2*)(oh + i)     = __halves2half2(h0, h1);
    *(__half2*)(oh + i + 2) = __halves2half2(h2, h3);
    *(__half2*)(ol + i)     = __halves2half2(__float2half_rn(v.x - __half2float(h0)),
                                             __float2half_rn(v.y - __half2float(h1)));
    *(__half2*)(ol + i + 2) = __halves2half2(__float2half_rn(v.z - __half2float(h2)),
                                             __float2half_rn(v.w - __half2float(h3)));
}

// Q: [bh][t][128] <- g_q[(b*T+t)][h*128+d]
__global__ __launch_bounds__(256)
void conv_q(const float* __restrict__ q, __half* __restrict__ oh, __half* __restrict__ ol)
{
    long i4 = (long)blockIdx.x*blockDim.x + threadIdx.x;
    if (i4 >= (long)BB*HH*TT*32) return;
    long i = i4*4;
    int d = (int)(i & 127); long r = i >> 7;
    int t = (int)(r & (TT-1)); int bh = (int)(r >> 11);
    int hh = bh & 15, bb = bh >> 4;
    float4 v = *(const float4*)&q[((size_t)(bb*TT + t))*2048 + hh*128 + d];
    split_store4(v, oh, ol, (size_t)i);
}

// K: [bh][t][128]: d<64 from kv, d>=64 from ckv rope cols (head-broadcast)
__global__ __launch_bounds__(256)
void conv_k(const float* __restrict__ kv, const float* __restrict__ ckv,
            __half* __restrict__ oh, __half* __restrict__ ol)
{
    long i4 = (long)blockIdx.x*blockDim.x + threadIdx.x;
    if (i4 >= (long)BB*HH*TT*32) return;
    long i = i4*4;
    int d = (int)(i & 127); long r = i >> 7;
    int t = (int)(r & (TT-1)); int bh = (int)(r >> 11);
    int hh = bh & 15, bb = bh >> 4;
    float4 v;
    if (d < 64) v = *(const float4*)&kv [((size_t)(bb*TT + t))*1024 + hh*64 + d];
    else        v = *(const float4*)&ckv[((size_t)(bb*TT + t))*576 + 512 + (d - 64)];
    split_store4(v, oh, ol, (size_t)i);
}

// V: [bh][t][64] from kv
__global__ __launch_bounds__(256)
void conv_v(const float* __restrict__ kv, __half* __restrict__ oh, __half* __restrict__ ol)
{
    long i4 = (long)blockIdx.x*blockDim.x + threadIdx.x;
    if (i4 >= (long)BB*HH*TT*16) return;
    long i = i4*4;
    int d = (int)(i & 63); long r = i >> 6;
    int t = (int)(r & (TT-1)); int bh = (int)(r >> 11);
    int hh = bh & 15, bb = bh >> 4;
    float4 v = *(const float4*)&kv[((size_t)(bb*TT + t))*1024 + hh*64 + d];
    split_store4(v, oh, ol, (size_t)i);
}

// =====================================================================
// fp16-split HMMA GEMM (unchanged from R5, validated)
// =====================================================================
#define STAGE_BYTES 32768
#define HG_STAGES   3
#define HG_SMEM     (STAGE_BYTES*HG_STAGES)

__global__ __launch_bounds__(256, 1)
void hgemm(const __half* __restrict__ Ah, const __half* __restrict__ Al,
           const __half* __restrict__ Bh, const __half* __restrict__ Bl,
           float* __restrict__ C, int K, int ldc, int Nvalid)
{
    extern __shared__ char smem[];
    const uint32_t sb = smem_u32(smem);
    const int tid  = threadIdx.x;
    const int wid  = tid >> 5, lane = tid & 31;
    const int row0 = blockIdx.y * 128;
    const int col0 = blockIdx.x * 128;
    const int wm   = wid >> 1;
    const int wn   = wid & 1;

    int l_line[2], l_s8[2], l_r[2], l_c[2];
    #pragma unroll
    for (int j = 0; j < 2; j++) {
        int idx = tid + j*256;
        l_line[j] = idx >> 3;
        l_s8[j]   = idx & 7;
        int v     = l_s8[j] ^ (l_line[j] & 7);
        l_r[j]    = l_line[j]*2 + (v >> 2);
        l_c[j]    = v & 3;
    }

#define LOAD_STAGE(CH, ST) do { \
    uint32_t _base = sb + (uint32_t)(ST)*STAGE_BYTES; \
    _Pragma("unroll") \
    for (int _a = 0; _a < 4; _a++) { \
        const __half* _src = (_a == 0) ? Ah : (_a == 1) ? Al : (_a == 2) ? Bh : Bl; \
        int _rb = (_a < 2) ? row0 : col0; \
        _Pragma("unroll") \
        for (int _j = 0; _j < 2; _j++) { \
            const void* _g = _src + (size_t)(_rb + l_r[_j])*(size_t)K \
                             + (CH)*32 + l_c[_j]*8; \
            CP_ASYNC16(_base + _a*8192u + (uint32_t)(l_line[_j]*128 + l_s8[_j]*16), _g); \
        } \
    } \
    CP_COMMIT(); \
} while (0)

    float acc[2][8][4];
    #pragma unroll
    for (int mi = 0; mi < 2; mi++)
        #pragma unroll
        for (int nj = 0; nj < 8; nj++)
            #pragma unroll
            for (int e = 0; e < 4; e++) acc[mi][nj][e] = 0.f;

    const int nch = K >> 5;
    LOAD_STAGE(0, 0);
    LOAD_STAGE(1, 1);

    const int lr8 = (lane & 7) + ((lane >> 3) & 1)*8;
    const int chx = (lane >> 4);

    int st = 0;
    for (int ch = 0; ch < nch; ch++) {
        if (ch + 2 < nch) { CP_WAIT(1); } else { CP_WAIT(0); }
        __syncthreads();
        if (ch + 2 < nch) {
            int st2 = st + 2; if (st2 >= HG_STAGES) st2 -= HG_STAGES;
            LOAD_STAGE(ch + 2, st2);
        }

        const uint32_t base = sb + (uint32_t)st*STAGE_BYTES;
        #pragma unroll
        for (int kk = 0; kk < 2; kk++) {
            const int cc = kk*2 + chx;
            uint32_t a_h[2][4], a_l[2][4], b_h[4][4], b_l[4][4];

            #pragma unroll
            for (int mi = 0; mi < 2; mi++) {
                int r = wm*32 + mi*16 + lr8;
                uint32_t off = (uint32_t)((r >> 1)*128 +
                    (((cc | ((r & 1) << 2)) ^ ((r >> 1) & 7)) << 4));
                LDSM4(a_h[mi], base + off);
                LDSM4(a_l[mi], base + 8192u + off);
            }
            #pragma unroll
            for (int nb = 0; nb < 4; nb++) {
                int r = wn*64 + nb*16 + lr8;
                uint32_t off = (uint32_t)((r >> 1)*128 +
                    (((cc | ((r & 1) << 2)) ^ ((r >> 1) & 7)) << 4));
                LDSM4(b_h[nb], base + 16384u + off);
                LDSM4(b_l[nb], base + 24576u + off);
            }

            #pragma unroll
            for (int mi = 0; mi < 2; mi++)
                #pragma unroll
                for (int nb = 0; nb < 4; nb++)
                    #pragma unroll
                    for (int nn = 0; nn < 2; nn++) {
                        float* d = acc[mi][nb*2 + nn];
                        MMA16816(d, a_h[mi], b_h[nb][nn], b_h[nb][nn+2]);
                        MMA16816(d, a_h[mi], b_l[nb][nn], b_l[nb][nn+2]);
                        MMA16816(d, a_l[mi], b_h[nb][nn], b_h[nb][nn+2]);
                    }
        }
        st++; if (st >= HG_STAGES) st = 0;
    }

    #pragma unroll
    for (int mi = 0; mi < 2; mi++) {
        int m = row0 + wm*32 + mi*16 + (lane >> 2);
        #pragma unroll
        for (int nb = 0; nb < 4; nb++)
            #pragma unroll
            for (int nn = 0; nn < 2; nn++) {
                int col = col0 + wn*64 + nb*16 + nn*8 + (lane & 3)*2;
                if (col < Nvalid) {
                    const float* d = acc[mi][nb*2 + nn];
                    *(float2*)&C[(size_t)m*ldc + col]       = make_float2(d[0], d[1]);
                    *(float2*)&C[(size_t)(m + 8)*ldc + col] = make_float2(d[2], d[3]);
                }
            }
    }
}

// =====================================================================
// RoPE in place
// =====================================================================
__global__ __launch_bounds__(256)
void rope_kernel()
{
    const int nq = MTOT * HH * (RDIM/2);
    const int nk = MTOT * (RDIM/2);
    int idx = blockIdx.x * blockDim.x + threadIdx.x;
    if (idx >= nq + nk) return;
    float* p; int t, i;
    if (idx < nq) {
        i = idx & 31;
        int r = idx >> 5;
        int h = r & (HH-1);
        int m = r >> 4;
        t = m & (TT-1);
        p = g_q + (size_t)m*(HH*HDD) + h*HDD + NDIM + 2*i;
    } else {
        int j = idx - nq;
        i = j & 31;
        int m = j >> 5;
        t = m & (TT-1);
        p = g_ckv + (size_t)m*CKVW + LORA_ + 2*i;
    }
    float freq = powf(100000.0f, -(float)i * (1.0f/32.0f));
    float sn, cs; sincosf((float)t * freq, &sn, &cs);
    float x0 = p[0], x1 = p[1];
    p[0] = x0*cs - x1*sn;
    p[1] = x0*sn + x1*cs;
}

// =====================================================================
// HMMA causal flash attention.
// CTA: 128 queries (8 warps x m16) for one (qt,h,b); key tiles of 64.
// S = QK^T with 3-way fp16 split; softmax; PV with P fp16 + V hi/lo.
// Output written directly as o-proj hi/lo operand (a6h/a6l).
// smem: Qh[0,32K) Ql[32K,64K) + 2 stages of {Kh 16K, Kl 16K, Vh 8K, Vl 8K}.
// =====================================================================
#define ATM_SCALE 0.08838834764831845f
#define ATM_STAGE 49152
#define ATM_SMEM  (65536 + 2*ATM_STAGE)   /* 163840 */

__global__ __launch_bounds__(256, 1)
void attn_mma(const __half* __restrict__ Qh, const __half* __restrict__ Ql,
              const __half* __restrict__ Kh, const __half* __restrict__ Kl,
              const __half* __restrict__ Vh, const __half* __restrict__ Vl,
              __half* __restrict__ Oh, __half* __restrict__ Ol)
{
    extern __shared__ char smem[];
    const uint32_t sb = smem_u32(smem);
    const int tid  = threadIdx.x;
    const int wm   = tid >> 5, lane = tid & 31;
    const int qt   = (int)gridDim.x - 1 - (int)blockIdx.x;  // heavy CTAs first
    const int h    = blockIdx.y, b = blockIdx.z;
    const int bh   = b*HH + h;
    const int t0   = qt * 128;
    const size_t qrow  = ((size_t)bh*TT + t0)*128;
    const size_t krow0 = (size_t)bh*TT*128;
    const size_t vrow0 = (size_t)bh*TT*64;

    // Q (hi/lo) -> swizzled smem (rows 256B, 16 slots of 16B, slot^=(r&7))
    for (int i = tid; i < 2048; i += 256) {
        int r = i >> 4, s = i & 15;
        uint32_t ph = (uint32_t)(r*256 + ((s ^ (r & 7)) << 4));
        *(uint4*)(smem + ph)         = *(const uint4*)(Qh + qrow + (size_t)r*128 + s*8);
        *(uint4*)(smem + 32768 + ph) = *(const uint4*)(Ql + qrow + (size_t)r*128 + s*8);
    }

    const int lr8 = (lane & 7) + ((lane >> 3) & 1)*8;
    const int chx = lane >> 4;

    float o_acc[8][4];
    #pragma unroll
    for (int j = 0; j < 8; j++)
        #pragma unroll
        for (int e = 0; e < 4; e++) o_acc[j][e] = 0.f;
    float m0 = -1e30f, m1 = -1e30f, l0 = 0.f, l1 = 0.f;

    const int nkt = 2*qt + 2;

#define ATM_PRE(KT, ST) do { \
    uint32_t bs = sb + 65536 + (uint32_t)(ST)*ATM_STAGE; \
    const __half* kh_ = Kh + krow0 + (size_t)(KT)*64*128; \
    const __half* kl_ = Kl + krow0 + (size_t)(KT)*64*128; \
    const __half* vh_ = Vh + vrow0 + (size_t)(KT)*64*64; \
    const __half* vl_ = Vl + vrow0 + (size_t)(KT)*64*64; \
    for (int i = tid; i < 1024; i += 256) { \
        int r = i >> 4, s = i & 15; \
        uint32_t ph = (uint32_t)(r*256 + ((s ^ (r & 7)) << 4)); \
        CP_ASYNC16(bs + ph,         kh_ + (size_t)r*128 + s*8); \
        CP_ASYNC16(bs + 16384 + ph, kl_ + (size_t)r*128 + s*8); \
    } \
    for (int i = tid; i < 512; i += 256) { \
        int r = i >> 3, s = i & 7; \
        uint32_t ph = (uint32_t)(r*128 + ((s ^ (r & 7)) << 4)); \
        CP_ASYNC16(bs + 32768 + ph, vh_ + (size_t)r*64 + s*8); \
        CP_ASYNC16(bs + 40960 + ph, vl_ + (size_t)r*64 + s*8); \
    } \
    CP_COMMIT(); \
} while (0)

    ATM_PRE(0, 0);

    for (int kt = 0; kt < nkt; kt++) {
        const int st = kt & 1;
        CP_WAIT(0);
        __syncthreads();                 // stage kt ready; all warps done with kt-1
        if (kt + 1 < nkt) ATM_PRE(kt + 1, st ^ 1);

        const uint32_t ks = sb + 65536 + (uint32_t)st*ATM_STAGE;

        // ---- S = Q K^T  (3-way split) ----
        float sacc[8][4];
        #pragma unroll
        for (int j = 0; j < 8; j++)
            #pragma unroll
            for (int e = 0; e < 4; e++) sacc[j][e] = 0.f;

        #pragma unroll
        for (int cc = 0; cc < 8; cc++) {
            uint32_t aqh[4], aql[4];
            {
                int r = wm*16 + lr8;
                int s = cc*2 + chx;
                uint32_t off = (uint32_t)(r*256 + ((s ^ (r & 7)) << 4));
                LDSM4(aqh, sb + off);
                LDSM4(aql, sb + 32768u + off);
            }
            #pragma unroll
            for (int nb = 0; nb < 4; nb++) {
                uint32_t bkh[4], bkl[4];
                int rn = nb*16 + lr8;
                int s = cc*2 + chx;
                uint32_t off = (uint32_t)(rn*256 + ((s ^ (rn & 7)) << 4));
                LDSM4(bkh, ks + off);
                LDSM4(bkl, ks + 16384u + off);
                MMA16816(sacc[nb*2],     aqh, bkh[0], bkh[2]);
                MMA16816(sacc[nb*2],     aqh, bkl[0], bkl[2]);
                MMA16816(sacc[nb*2],     aql, bkh[0], bkh[2]);
                MMA16816(sacc[nb*2 + 1], aqh, bkh[1], bkh[3]);
                MMA16816(sacc[nb*2 + 1], aqh, bkl[1], bkl[3]);
                MMA16816(sacc[nb*2 + 1], aql, bkh[1], bkh[3]);
            }
        }

        // ---- causal mask (only last two tiles intersect the diagonal) ----
        if (kt >= 2*qt) {
            int s0 = kt*64;
            int rb = t0 + wm*16 + (lane >> 2);
            #pragma unroll
            for (int j = 0; j < 8; j++) {
                int c0 = s0 + j*8 + (lane & 3)*2;
                if (c0     > rb)     sacc[j][0] = -3.0e38f;
                if (c0 + 1 > rb)     sacc[j][1] = -3.0e38f;
                if (c0     > rb + 8) sacc[j][2] = -3.0e38f;
                if (c0 + 1 > rb + 8) sacc[j][3] = -3.0e38f;
            }
        }

        // ---- online softmax (rows r=(lane>>2) and r+8; quad-reduced) ----
        float rm0 = -3.0e38f, rm1 = -3.0e38f;
        #pragma unroll
        for (int j = 0; j < 8; j++) {
            rm0 = fmaxf(rm0, fmaxf(sacc[j][0], sacc[j][1]));
            rm1 = fmaxf(rm1, fmaxf(sacc[j][2], sacc[j][3]));
        }
        rm0 = fmaxf(rm0, __shfl_xor_sync(0xffffffffu, rm0, 1));
        rm0 = fmaxf(rm0, __shfl_xor_sync(0xffffffffu, rm0, 2));
        rm1 = fmaxf(rm1, __shfl_xor_sync(0xffffffffu, rm1, 1));
        rm1 = fmaxf(rm1, __shfl_xor_sync(0xffffffffu, rm1, 2));
        float mn0 = fmaxf(m0, rm0), mn1 = fmaxf(m1, rm1);
        float f0  = __expf(ATM_SCALE*(m0 - mn0));
        float f1  = __expf(ATM_SCALE*(m1 - mn1));
        m0 = mn0; m1 = mn1;
        float rs0 = 0.f, rs1 = 0.f;
        #pragma unroll
        for (int j = 0; j < 8; j++) {
            sacc[j][0] = __expf(ATM_SCALE*(sacc[j][0] - mn0)); rs0 += sacc[j][0];
            sacc[j][1] = __expf(ATM_SCALE*(sacc[j][1] - mn0)); rs0 += sacc[j][1];
            sacc[j][2] = __expf(ATM_SCALE*(sacc[j][2] - mn1)); rs1 += sacc[j][2];
            sacc[j][3] = __expf(ATM_SCALE*(sacc[j][3] - mn1)); rs1 += sacc[j][3];
        }
        rs0 += __shfl_xor_sync(0xffffffffu, rs0, 1);
        rs0 += __shfl_xor_sync(0xffffffffu, rs0, 2);
        rs1 += __shfl_xor_sync(0xffffffffu, rs1, 1);
        rs1 += __shfl_xor_sync(0xffffffffu, rs1, 2);
        l0 = l0*f0 + rs0; l1 = l1*f1 + rs1;
        #pragma unroll
        for (int j = 0; j < 8; j++) {
            o_acc[j][0] *= f0; o_acc[j][1] *= f0;
            o_acc[j][2] *= f1; o_acc[j][3] *= f1;
        }

        // ---- P fragments (C-layout -> A-layout, FA2 trick) ----
        uint32_t pf[4][4];
        #pragma unroll
        for (int kk = 0; kk < 4; kk++) {
            pf[kk][0] = h2u(__floats2half2_rn(sacc[2*kk][0],     sacc[2*kk][1]));
            pf[kk][1] = h2u(__floats2half2_rn(sacc[2*kk][2],     sacc[2*kk][3]));
            pf[kk][2] = h2u(__floats2half2_rn(sacc[2*kk + 1][0], sacc[2*kk + 1][1]));
            pf[kk][3] = h2u(__floats2half2_rn(sacc[2*kk + 1][2], sacc[2*kk + 1][3]));
        }

        // ---- O += P V  (V hi/lo; B frags via ldmatrix.trans: {t0,t1},{t2,t3}) ----
        #pragma unroll
        for (int kk = 0; kk < 4; kk++) {
            #pragma unroll
            for (int nb = 0; nb < 4; nb++) {
                uint32_t bvh[4], bvl[4];
                int rv = kk*16 + lr8;
                int s = nb*2 + chx;
                uint32_t off = (uint32_t)(rv*128 + ((s ^ (rv & 7)) << 4));
                LDSM4T(bvh, ks + 32768u + off);
                LDSM4T(bvl, ks + 40960u + off);
                MMA16816(o_acc[nb*2],     pf[kk], bvh[0], bvh[1]);
                MMA16816(o_acc[nb*2],     pf[kk], bvl[0], bvl[1]);
                MMA16816(o_acc[nb*2 + 1], pf[kk], bvh[2], bvh[3]);
                MMA16816(o_acc[nb*2 + 1], pf[kk], bvl[2], bvl[3]);
            }
        }
    }

    // ---- epilogue: normalize, hi/lo split, write o-proj operand ----
    float il0 = 1.0f/l0, il1 = 1.0f/l1;
    int r0g = b*TT + t0 + wm*16 + (lane >> 2);
    size_t ob0 = (size_t)r0g*KVW + h*64;
    size_t ob1 = ob0 + (size_t)8*KVW;
    #pragma unroll
    for (int j = 0; j < 8; j++) {
        int d = j*8 + (lane & 3)*2;
        float v0 = o_acc[j][0]*il0, v1 = o_acc[j][1]*il0;
        float v2 = o_acc[j][2]*il1, v3 = o_acc[j][3]*il1;
        __half h0 = __float2half_rn(v0), h1 = __float2half_rn(v1);
        __half h2v = __float2half_rn(v2), h3 = __float2half_rn(v3);
        *(__half2*)(Oh + ob0 + d) = __halves2half2(h0, h1);
        *(__half2*)(Oh + ob1 + d) = __halves2half2(h2v, h3);
        *(__half2*)(Ol + ob0 + d) = __halves2half2(__float2half_rn(v0 - __half2float(h0)),
                                                   __float2half_rn(v1 - __half2float(h1)));
        *(__half2*)(Ol + ob1 + d) = __halves2half2(__float2half_rn(v2 - __half2float(h2v)),
                                                   __float2half_rn(v3 - __half2float(h3)));
    }
}

// =====================================================================
// launch
// =====================================================================
extern "C" void kernel_launch(void* const* d_in, const int* in_sizes, int n_in,
                              void* d_out, int out_size)
{
    const float* x    = (const float*)d_in[0];
    const float* Wq   = (const float*)d_in[1];
    const float* Wkva = (const float*)d_in[2];
    const float* Wkvb = (const float*)d_in[3];
    const float* Wo   = (const float*)d_in[4];
    float* out        = (float*)d_out;

    float *gq, *gckv, *gkv;
    cudaGetSymbolAddress((void**)&gq,   g_q);
    cudaGetSymbolAddress((void**)&gckv, g_ckv);
    cudaGetSymbolAddress((void**)&gkv,  g_kv);

    __half *xh,*xl,*wqh,*wql,*wah,*wal,*wbh,*wbl,*woh,*wol,*a4h,*a4l,*a6h,*a6l;
    __half *Qh,*Ql,*Kh,*Kl,*Vh,*Vl;
    cudaGetSymbolAddress((void**)&xh,  g_xh);  cudaGetSymbolAddress((void**)&xl,  g_xl);
    cudaGetSymbolAddress((void**)&wqh, g_wqh); cudaGetSymbolAddress((void**)&wql, g_wql);
    cudaGetSymbolAddress((void**)&wah, g_wah); cudaGetSymbolAddress((void**)&wal, g_wal);
    cudaGetSymbolAddress((void**)&wbh, g_wbh); cudaGetSymbolAddress((void**)&wbl, g_wbl);
    cudaGetSymbolAddress((void**)&woh, g_woh); cudaGetSymbolAddress((void**)&wol, g_wol);
    cudaGetSymbolAddress((void**)&a4h, g_a4h); cudaGetSymbolAddress((void**)&a4l, g_a4l);
    cudaGetSymbolAddress((void**)&a6h, g_a6h); cudaGetSymbolAddress((void**)&a6l, g_a6l);
    cudaGetSymbolAddress((void**)&Qh,  g_Qh);  cudaGetSymbolAddress((void**)&Ql,  g_Ql);
    cudaGetSymbolAddress((void**)&Kh,  g_Kh);  cudaGetSymbolAddress((void**)&Kl,  g_Kl);
    cudaGetSymbolAddress((void**)&Vh,  g_Vh);  cudaGetSymbolAddress((void**)&Vl,  g_Vl);

    cudaFuncSetAttribute(hgemm, cudaFuncAttributeMaxDynamicSharedMemorySize, HG_SMEM);
    cudaFuncSetAttribute(attn_mma, cudaFuncAttributeMaxDynamicSharedMemorySize, ATM_SMEM);

    dim3 blk(256);

    // weight prep
    transpose_convert<<<dim3(2048/32, 2048/32), blk>>>(Wq,   2048, 2048, 0, wqh, wql);
    transpose_convert<<<dim3(2048/32, NAPAD/32), blk>>>(Wkva, CKVW, 2048, 0, wah, wal);
    transpose_convert<<<dim3(512/32,  1024/32), blk>>>(Wkvb, 1024, 512,  0, wbh, wbl);
    transpose_convert<<<dim3(1024/32, 2048/32), blk>>>(Wo,   2048, 1024, 1, woh, wol);

    // x -> hi/lo
    convert_rows<<<4096, blk>>>(x, CCH, (long)MTOT*CCH, CCH, xh, xl);

    // 1) q = x @ Wq^T
    hgemm<<<dim3(2048/128, MTOT/128), blk, HG_SMEM>>>(xh, xl, wqh, wql, gq,
        2048, 2048, 2048);
    // 2) ckv = x @ Wkva
    hgemm<<<dim3(NAPAD/128, MTOT/128), blk, HG_SMEM>>>(xh, xl, wah, wal, gckv,
        2048, CKVW, CKVW);

    // 3) rope in place
    {
        int total = MTOT*HH*(RDIM/2) + MTOT*(RDIM/2);
        rope_kernel<<<(total + 255)/256, blk>>>();
    }

    // 4) kv = latent @ Wkvb
    convert_rows<<<2048, blk>>>(gckv, CKVW, (long)MTOT*LORA_, LORA_, a4h, a4l);
    hgemm<<<dim3(KVW/128, MTOT/128), blk, HG_SMEM>>>(a4h, a4l, wbh, wbl, gkv,
        512, KVW, KVW);

    // 5) attention operand prep + attention (writes a6h/a6l directly)
    conv_q<<<8192, blk>>>(gq, Qh, Ql);
    conv_k<<<8192, blk>>>(gkv, gckv, Kh, Kl);
    conv_v<<<4096, blk>>>(gkv, Vh, Vl);
    attn_mma<<<dim3(TT/128, HH, BB), blk, ATM_SMEM>>>(Qh, Ql, Kh, Kl, Vh, Vl, a6h, a6l);

    // 6) out = y_nope @ Wo[nope rows]
    hgemm<<<dim3(2048/128, MTOT/128), blk, HG_SMEM>>>(a6h, a6l, woh, wol, out,
        1024, CCH, CCH);
}